// round 14
// baseline (speedup 1.0000x reference)
#include <cuda_runtime.h>
#include <cuda_fp16.h>

#define NN 8192
#define CC 16
#define KAUG 24          // halves per augmented row (16 used), 48B stride (conflict-free)
#define UPAD 136
#define THREADS 256
#define ITILE 256

// ---------------- device scratch ----------------
__device__ __align__(16) __half g_Aaug[NN * KAUG];
__device__ __align__(16) __half g_Baug[NN * KAUG];
__device__ __align__(16) __half g_UT[64 * CC * 128];   // [tile][c][j]

// smem layout (in halves)
#define SA  0                      // 256*24 = 6144
#define SB  6144                   // 128*24 = 3072
#define SU  9216                   // 16*136 = 2176
#define SMEM_HALVES 11392
#define SMEM_BYTES (SMEM_HALVES * 2)   // 22784 B

// ---------------- helpers ----------------
__device__ __forceinline__ unsigned s2u(const void* p) {
    return (unsigned)__cvta_generic_to_shared(p);
}
__device__ __forceinline__ unsigned ex2h(unsigned x) {
    unsigned y; asm("ex2.approx.f16x2 %0, %1;" : "=r"(y) : "r"(x)); return y;
}
__device__ __forceinline__ void ldsm4(unsigned& r0, unsigned& r1, unsigned& r2, unsigned& r3, unsigned a) {
    asm volatile("ldmatrix.sync.aligned.m8n8.x4.shared.b16 {%0,%1,%2,%3}, [%4];"
                 : "=r"(r0), "=r"(r1), "=r"(r2), "=r"(r3) : "r"(a));
}
// GEMM1: f16 accumulators (rt ~8), C = 0, logits emerge packed f16x2
__device__ __forceinline__ void mma16816h(unsigned& d0, unsigned& d1,
                                          unsigned a0, unsigned a1, unsigned a2, unsigned a3,
                                          unsigned b0, unsigned b1) {
    asm volatile("mma.sync.aligned.m16n8k16.row.col.f16.f16.f16.f16 "
                 "{%0,%1}, {%2,%3,%4,%5}, {%6,%7}, {%8,%9};"
                 : "=r"(d0), "=r"(d1)
                 : "r"(a0), "r"(a1), "r"(a2), "r"(a3), "r"(b0), "r"(b1),
                   "r"(0u), "r"(0u));
}
// GEMM2: f32 accumulators
__device__ __forceinline__ void mma16816(float* c, unsigned a0, unsigned a1, unsigned a2, unsigned a3,
                                         unsigned b0, unsigned b1) {
    asm volatile("mma.sync.aligned.m16n8k16.row.col.f32.f16.f16.f32 "
                 "{%0,%1,%2,%3}, {%4,%5,%6,%7}, {%8,%9}, {%0,%1,%2,%3};"
                 : "+f"(c[0]), "+f"(c[1]), "+f"(c[2]), "+f"(c[3])
                 : "r"(a0), "r"(a1), "r"(a2), "r"(a3), "r"(b0), "r"(b1));
}
__device__ __forceinline__ void cp16(unsigned saddr, const void* g) {
    asm volatile("cp.async.ca.shared.global [%0], [%1], 16;" :: "r"(saddr), "l"(g));
}
#define CP_COMMIT() asm volatile("cp.async.commit_group;" ::: "memory")

// ---------------- pre-kernel: 64 blocks x 256 threads, 128 rows each ----------------
__global__ __launch_bounds__(256) void lg_pre_kernel(const float* __restrict__ U,
                                                     const float* __restrict__ ref,
                                                     float* __restrict__ out) {
    __shared__ __half sUh[128 * 17];
    const int b = blockIdx.x;
    const int tid = threadIdx.x;

#pragma unroll
    for (int k = 0; k < 8; k++) {
        int idx = k * 256 + tid;
        float f = U[b * 2048 + idx];
        out[b * 2048 + idx] = -f;
        sUh[(idx >> 4) * 17 + (idx & 15)] = __float2half_rn(f);
    }
    __syncthreads();

    unsigned* gUTu = (unsigned*)g_UT;
#pragma unroll
    for (int k = 0; k < 4; k++) {
        int w = k * 256 + tid;
        int c  = w >> 6;
        int j2 = w & 63;
        __half h0 = sUh[(2 * j2) * 17 + c];
        __half h1 = sUh[(2 * j2 + 1) * 17 + c];
        unsigned v = (unsigned)__half_as_ushort(h0) | ((unsigned)__half_as_ushort(h1) << 16);
        gUTu[((size_t)b * 16 + c) * 64 + j2] = v;
    }

    if (tid < 128) {
        const int i = b * 128 + tid;
        const float SC = 1.2011224087864498f;  // sqrt(log2 e)
        float rs[5], ss = 0.f;
#pragma unroll
        for (int k = 0; k < 5; k++) { rs[k] = ref[i * 5 + k] * SC; ss += rs[k] * rs[k]; }
        float c = -0.5f * ss;
        unsigned short rh[5], rl[5], chh, cll;
#pragma unroll
        for (int k = 0; k < 5; k++) {
            __half hh = __float2half_rn(rs[k]);
            rh[k] = __half_as_ushort(hh);
            rl[k] = __half_as_ushort(__float2half_rn(rs[k] - __half2float(hh)));
        }
        {
            __half hc = __float2half_rn(c);
            chh = __half_as_ushort(hc);
            cll = __half_as_ushort(__float2half_rn(c - __half2float(hc)));
        }
        const unsigned short ONE = 0x3C00;
        unsigned short A[KAUG], B[KAUG];
#pragma unroll
        for (int k = 0; k < KAUG; k++) { A[k] = 0; B[k] = 0; }
        // K=16 single-step pairing:
        // A: [rh(0-4), rl(5-9), chh, cll, 1, 1, 0, 0]
        // B: [rh(0-4), rh(5-9), 1, 1, chh, cll, 0, 0]
        // logit = rs_i . rh_j + c_i + c_j
#pragma unroll
        for (int k = 0; k < 5; k++) { A[k] = rh[k]; A[5 + k] = rl[k]; }
        A[10] = chh; A[11] = cll; A[12] = ONE; A[13] = ONE;
#pragma unroll
        for (int k = 0; k < 5; k++) { B[k] = rh[k]; B[5 + k] = rh[k]; }
        B[10] = ONE; B[11] = ONE; B[12] = chh; B[13] = cll;
        uint4* gA = (uint4*)(g_Aaug + (size_t)i * KAUG);
        uint4* gB = (uint4*)(g_Baug + (size_t)i * KAUG);
#pragma unroll
        for (int q = 0; q < 3; q++) {
            gA[q] = ((const uint4*)A)[q];
            gB[q] = ((const uint4*)B)[q];
        }
    }
}

// ---------------- main kernel: one (i256 x j128) tile per CTA, m32 per warp, occ 4 ----------------
__global__ __launch_bounds__(THREADS, 4) void lg_main_kernel(float* __restrict__ out) {
    extern __shared__ __align__(16) __half smem[];

    const int tid = threadIdx.x;
    const int w = tid >> 5;
    const int l = tid & 31;
    const int bx = blockIdx.x;   // i-tile (256 rows)
    const int by = blockIdx.y;   // j-tile (128 rows)

    const unsigned sAb = s2u(smem + SA);
    const unsigned sBb = s2u(smem + SB);
    const unsigned sUb = s2u(smem + SU);

    // ---- prologue: load A (256x48B), B (128x48B), U (16x256B) ----
    {
        const char* gA = (const char*)(g_Aaug) + (size_t)bx * ITILE * KAUG * 2;
        for (int k = tid; k < 768; k += THREADS) cp16(sAb + k * 16, gA + k * 16);
        const char* gB = (const char*)(g_Baug) + (size_t)by * 128 * KAUG * 2;
        for (int k = tid; k < 384; k += THREADS) cp16(sBb + k * 16, gB + k * 16);
        const char* gU = (const char*)(g_UT) + (size_t)by * CC * 256;
        for (int k = tid; k < 256; k += THREADS) {
            int row = k >> 4, q = k & 15;
            cp16(sUb + row * (UPAD * 2) + q * 16, gU + k * 16);
        }
        CP_COMMIT();
    }

    // lane address pieces
    const int lrowB = ((l >> 4) & 1) * 8 + (l & 7);
    const int lkB   = ((l >> 3) & 1) * 16;
    const int lrowA = ((l >> 3) & 1) * 8 + (l & 7);
    const int lkA   = ((l >> 4) & 1) * 16;

    const unsigned aAddr = sAb + (w * 32 + lrowA) * (KAUG * 2) + lkA;

    float o0[2][4], o1[2][4];
#pragma unroll
    for (int nb = 0; nb < 2; nb++)
#pragma unroll
        for (int q = 0; q < 4; q++) { o0[nb][q] = 0.f; o1[nb][q] = 0.f; }

    asm volatile("cp.async.wait_group 0;" ::: "memory");
    __syncthreads();

    // A fragments: 2 m-blocks, 1 k16 step each
    unsigned aF0[4], aF1[4];
    ldsm4(aF0[0], aF0[1], aF0[2], aF0[3], aAddr);
    ldsm4(aF1[0], aF1[1], aF1[2], aF1[3], aAddr + 16 * (KAUG * 2));

#pragma unroll
    for (int p = 0; p < 8; p++) {
        unsigned b0, b1, b2, b3;
        ldsm4(b0, b1, b2, b3, sBb + (p * 16 + lrowB) * (KAUG * 2) + lkB);
        unsigned u0, u1, u2, u3;
        ldsm4(u0, u1, u2, u3, sUb + lrowB * (UPAD * 2) + p * 32 + lkB);

        // m-block 0: f16-accum logits -> packed exp
        unsigned w00, w01, w02, w03;
        {
            unsigned d0, d1, d2, d3;
            mma16816h(d0, d1, aF0[0], aF0[1], aF0[2], aF0[3], b0, b1);
            mma16816h(d2, d3, aF0[0], aF0[1], aF0[2], aF0[3], b2, b3);
            w00 = ex2h(d0);
            w01 = ex2h(d1);
            w02 = ex2h(d2);
            w03 = ex2h(d3);
        }
        // m-block 1
        unsigned w10, w11, w12, w13;
        {
            unsigned d0, d1, d2, d3;
            mma16816h(d0, d1, aF1[0], aF1[1], aF1[2], aF1[3], b0, b1);
            mma16816h(d2, d3, aF1[0], aF1[1], aF1[2], aF1[3], b2, b3);
            w10 = ex2h(d0);
            w11 = ex2h(d1);
            w12 = ex2h(d2);
            w13 = ex2h(d3);
        }

        mma16816(o0[0], w00, w01, w02, w03, u0, u1);
        mma16816(o0[1], w00, w01, w02, w03, u2, u3);
        mma16816(o1[0], w10, w11, w12, w13, u0, u1);
        mma16816(o1[1], w10, w11, w12, w13, u2, u3);
    }

    // ---- epilogue ----
    const int g = l >> 2;
    const int tq = l & 3;
    const int i0 = bx * ITILE + w * 32 + g;
#pragma unroll
    for (int nb = 0; nb < 2; nb++) {
        const int col = nb * 8 + tq * 2;
        atomicAdd(&out[i0 * CC + col],            o0[nb][0]);
        atomicAdd(&out[i0 * CC + col + 1],        o0[nb][1]);
        atomicAdd(&out[(i0 + 8) * CC + col],      o0[nb][2]);
        atomicAdd(&out[(i0 + 8) * CC + col + 1],  o0[nb][3]);
        atomicAdd(&out[(i0 + 16) * CC + col],     o1[nb][0]);
        atomicAdd(&out[(i0 + 16) * CC + col + 1], o1[nb][1]);
        atomicAdd(&out[(i0 + 24) * CC + col],     o1[nb][2]);
        atomicAdd(&out[(i0 + 24) * CC + col + 1], o1[nb][3]);
    }
}

extern "C" void kernel_launch(void* const* d_in, const int* in_sizes, int n_in,
                              void* d_out, int out_size) {
    const float* U   = (const float*)d_in[0];
    const float* ref = (const float*)d_in[1];
    float* out = (float*)d_out;

    static int attrSet = 0;
    if (!attrSet) {
        cudaFuncSetAttribute(lg_main_kernel, cudaFuncAttributeMaxDynamicSharedMemorySize, SMEM_BYTES);
        attrSet = 1;
    }

    lg_pre_kernel<<<64, 256>>>(U, ref, out);

    dim3 grid(NN / ITILE, NN / 128);
    lg_main_kernel<<<grid, THREADS, SMEM_BYTES>>>(out);
}

// round 15
// speedup vs baseline: 1.0083x; 1.0083x over previous
#include <cuda_runtime.h>
#include <cuda_fp16.h>

#define NN 8192
#define CC 16
#define KAUG 24          // halves per augmented row (16 used), 48B stride
#define UPAD 136
#define THREADS 256
#define ITILE 256

// smem layout (in halves)
#define SA  0                      // 256*24 = 6144
#define SB  6144                   // 128*24 = 3072
#define SU  9216                   // 16*136 = 2176
#define SMEM_HALVES 11392
#define SMEM_BYTES (SMEM_HALVES * 2)   // 22784 B

// ---------------- helpers ----------------
__device__ __forceinline__ unsigned s2u(const void* p) {
    return (unsigned)__cvta_generic_to_shared(p);
}
__device__ __forceinline__ unsigned ex2h(unsigned x) {
    unsigned y; asm("ex2.approx.f16x2 %0, %1;" : "=r"(y) : "r"(x)); return y;
}
__device__ __forceinline__ unsigned cvt2h(float hi, float lo) {
    unsigned d; asm("cvt.rn.f16x2.f32 %0, %1, %2;" : "=r"(d) : "f"(hi), "f"(lo)); return d;
}
__device__ __forceinline__ void ldsm4(unsigned& r0, unsigned& r1, unsigned& r2, unsigned& r3, unsigned a) {
    asm volatile("ldmatrix.sync.aligned.m8n8.x4.shared.b16 {%0,%1,%2,%3}, [%4];"
                 : "=r"(r0), "=r"(r1), "=r"(r2), "=r"(r3) : "r"(a));
}
__device__ __forceinline__ void mma16816(float* c, unsigned a0, unsigned a1, unsigned a2, unsigned a3,
                                         unsigned b0, unsigned b1) {
    asm volatile("mma.sync.aligned.m16n8k16.row.col.f32.f16.f16.f32 "
                 "{%0,%1,%2,%3}, {%4,%5,%6,%7}, {%8,%9}, {%0,%1,%2,%3};"
                 : "+f"(c[0]), "+f"(c[1]), "+f"(c[2]), "+f"(c[3])
                 : "r"(a0), "r"(a1), "r"(a2), "r"(a3), "r"(b0), "r"(b1));
}

// ---------------- init kernel: out = -U (128 blocks x 256 threads, float4) ----------------
__global__ __launch_bounds__(256) void lg_init_kernel(const float* __restrict__ U,
                                                      float* __restrict__ out) {
    const int idx = blockIdx.x * 256 + threadIdx.x;   // 32768 float4s
    float4 v = ((const float4*)U)[idx];
    ((float4*)out)[idx] = make_float4(-v.x, -v.y, -v.z, -v.w);
}

// ---------------- main kernel: fused build + (i256 x j128) tile, m32/warp, occ 4 ----------------
__global__ __launch_bounds__(THREADS, 4) void lg_main_kernel(const float* __restrict__ U,
                                                             const float* __restrict__ ref,
                                                             float* __restrict__ out) {
    extern __shared__ __align__(16) __half smem[];

    const int tid = threadIdx.x;
    const int w = tid >> 5;
    const int l = tid & 31;
    const int bx = blockIdx.x;   // i-tile (256 rows)
    const int by = blockIdx.y;   // j-tile (128 rows)

    const unsigned sAb = s2u(smem + SA);
    const unsigned sBb = s2u(smem + SB);
    const unsigned sUb = s2u(smem + SU);

    // ================= build phase =================
    const float SC = 1.2011224087864498f;  // sqrt(log2 e)
    const unsigned short ONE = 0x3C00;

    // ---- A row (all 256 threads): i = bx*256 + tid ----
    {
        const int i = bx * ITILE + tid;
        float rs[5], ss = 0.f;
#pragma unroll
        for (int k = 0; k < 5; k++) { rs[k] = __ldg(&ref[i * 5 + k]) * SC; ss += rs[k] * rs[k]; }
        float c = -0.5f * ss;
        unsigned short A[KAUG];
#pragma unroll
        for (int k = 0; k < KAUG; k++) A[k] = 0;
#pragma unroll
        for (int k = 0; k < 5; k++) {
            __half hh = __float2half_rn(rs[k]);
            A[k] = __half_as_ushort(hh);
            A[5 + k] = __half_as_ushort(__float2half_rn(rs[k] - __half2float(hh)));
        }
        {
            __half hc = __float2half_rn(c);
            A[10] = __half_as_ushort(hc);
            A[11] = __half_as_ushort(__float2half_rn(c - __half2float(hc)));
        }
        A[12] = ONE; A[13] = ONE;
        uint4* dst = (uint4*)(smem + SA + tid * KAUG);
#pragma unroll
        for (int q = 0; q < 3; q++) dst[q] = ((const uint4*)A)[q];
    }

    // ---- B row (threads 0..127): j = by*128 + tid ----
    if (tid < 128) {
        const int j = by * 128 + tid;
        float rs[5], ss = 0.f;
#pragma unroll
        for (int k = 0; k < 5; k++) { rs[k] = __ldg(&ref[j * 5 + k]) * SC; ss += rs[k] * rs[k]; }
        float c = -0.5f * ss;
        unsigned short B[KAUG];
#pragma unroll
        for (int k = 0; k < KAUG; k++) B[k] = 0;
#pragma unroll
        for (int k = 0; k < 5; k++) {
            unsigned short h = __half_as_ushort(__float2half_rn(rs[k]));
            B[k] = h; B[5 + k] = h;
        }
        B[10] = ONE; B[11] = ONE;
        {
            __half hc = __float2half_rn(c);
            B[12] = __half_as_ushort(hc);
            B[13] = __half_as_ushort(__float2half_rn(c - __half2float(hc)));
        }
        uint4* dst = (uint4*)(smem + SB + tid * KAUG);
#pragma unroll
        for (int q = 0; q < 3; q++) dst[q] = ((const uint4*)B)[q];
    }

    // ---- U^T tile: sU[c*UPAD + j_local] = f16(U[(by*128+j)*16 + c]) ----
    {
        const int jj = tid >> 1;                 // 0..127
        const int c0 = (tid & 1) * 8;            // 0 or 8
        const float4* up = (const float4*)(U + ((size_t)(by * 128 + jj)) * CC + c0);
        float4 v0 = __ldg(up);
        float4 v1 = __ldg(up + 1);
        __half* su = smem + SU;
        su[(c0 + 0) * UPAD + jj] = __float2half_rn(v0.x);
        su[(c0 + 1) * UPAD + jj] = __float2half_rn(v0.y);
        su[(c0 + 2) * UPAD + jj] = __float2half_rn(v0.z);
        su[(c0 + 3) * UPAD + jj] = __float2half_rn(v0.w);
        su[(c0 + 4) * UPAD + jj] = __float2half_rn(v1.x);
        su[(c0 + 5) * UPAD + jj] = __float2half_rn(v1.y);
        su[(c0 + 6) * UPAD + jj] = __float2half_rn(v1.z);
        su[(c0 + 7) * UPAD + jj] = __float2half_rn(v1.w);
    }

    __syncthreads();

    // ================= main loop (identical to R11) =================
    const int lrowB = ((l >> 4) & 1) * 8 + (l & 7);
    const int lkB   = ((l >> 3) & 1) * 16;
    const int lrowA = ((l >> 3) & 1) * 8 + (l & 7);
    const int lkA   = ((l >> 4) & 1) * 16;

    const unsigned aAddr = sAb + (w * 32 + lrowA) * (KAUG * 2) + lkA;

    float o0[2][4], o1[2][4];
#pragma unroll
    for (int nb = 0; nb < 2; nb++)
#pragma unroll
        for (int q = 0; q < 4; q++) { o0[nb][q] = 0.f; o1[nb][q] = 0.f; }

    unsigned aF0[4], aF1[4];
    ldsm4(aF0[0], aF0[1], aF0[2], aF0[3], aAddr);
    ldsm4(aF1[0], aF1[1], aF1[2], aF1[3], aAddr + 16 * (KAUG * 2));

#pragma unroll
    for (int p = 0; p < 8; p++) {
        unsigned b0, b1, b2, b3;
        ldsm4(b0, b1, b2, b3, sBb + (p * 16 + lrowB) * (KAUG * 2) + lkB);
        unsigned u0, u1, u2, u3;
        ldsm4(u0, u1, u2, u3, sUb + lrowB * (UPAD * 2) + p * 32 + lkB);

        // m-block 0
        unsigned w00, w01, w02, w03;
        {
            float s0[4] = {0.f, 0.f, 0.f, 0.f};
            float s1[4] = {0.f, 0.f, 0.f, 0.f};
            mma16816(s0, aF0[0], aF0[1], aF0[2], aF0[3], b0, b1);
            mma16816(s1, aF0[0], aF0[1], aF0[2], aF0[3], b2, b3);
            w00 = ex2h(cvt2h(s0[1], s0[0]));
            w01 = ex2h(cvt2h(s0[3], s0[2]));
            w02 = ex2h(cvt2h(s1[1], s1[0]));
            w03 = ex2h(cvt2h(s1[3], s1[2]));
        }
        // m-block 1
        unsigned w10, w11, w12, w13;
        {
            float s0[4] = {0.f, 0.f, 0.f, 0.f};
            float s1[4] = {0.f, 0.f, 0.f, 0.f};
            mma16816(s0, aF1[0], aF1[1], aF1[2], aF1[3], b0, b1);
            mma16816(s1, aF1[0], aF1[1], aF1[2], aF1[3], b2, b3);
            w10 = ex2h(cvt2h(s0[1], s0[0]));
            w11 = ex2h(cvt2h(s0[3], s0[2]));
            w12 = ex2h(cvt2h(s1[1], s1[0]));
            w13 = ex2h(cvt2h(s1[3], s1[2]));
        }

        mma16816(o0[0], w00, w01, w02, w03, u0, u1);
        mma16816(o0[1], w00, w01, w02, w03, u2, u3);
        mma16816(o1[0], w10, w11, w12, w13, u0, u1);
        mma16816(o1[1], w10, w11, w12, w13, u2, u3);
    }

    // ---- epilogue ----
    const int g = l >> 2;
    const int tq = l & 3;
    const int i0 = bx * ITILE + w * 32 + g;
#pragma unroll
    for (int nb = 0; nb < 2; nb++) {
        const int col = nb * 8 + tq * 2;
        atomicAdd(&out[i0 * CC + col],            o0[nb][0]);
        atomicAdd(&out[i0 * CC + col + 1],        o0[nb][1]);
        atomicAdd(&out[(i0 + 8) * CC + col],      o0[nb][2]);
        atomicAdd(&out[(i0 + 8) * CC + col + 1],  o0[nb][3]);
        atomicAdd(&out[(i0 + 16) * CC + col],     o1[nb][0]);
        atomicAdd(&out[(i0 + 16) * CC + col + 1], o1[nb][1]);
        atomicAdd(&out[(i0 + 24) * CC + col],     o1[nb][2]);
        atomicAdd(&out[(i0 + 24) * CC + col + 1], o1[nb][3]);
    }
}

extern "C" void kernel_launch(void* const* d_in, const int* in_sizes, int n_in,
                              void* d_out, int out_size) {
    const float* U   = (const float*)d_in[0];
    const float* ref = (const float*)d_in[1];
    float* out = (float*)d_out;

    static int attrSet = 0;
    if (!attrSet) {
        cudaFuncSetAttribute(lg_main_kernel, cudaFuncAttributeMaxDynamicSharedMemorySize, SMEM_BYTES);
        attrSet = 1;
    }

    lg_init_kernel<<<128, 256>>>(U, out);

    dim3 grid(NN / ITILE, NN / 128);
    lg_main_kernel<<<grid, THREADS, SMEM_BYTES>>>(U, ref, out);
}